// round 12
// baseline (speedup 1.0000x reference)
#include <cuda_runtime.h>

#define B_    32
#define H_    64
#define W_    64
#define K_    15
#define ZB_   64
#define NPIX  4096
#define NCH   79
#define TILE_PIX   128
#define TILES      32                 // per batch
#define TILE_F4    2528               // 128*316/16
#define TILE_WORDS 10112              // 128*79

#define NZBLK  60
#define NXYBLK (B_ * TILES)           // 1024
#define NBLK   (NZBLK + NXYBLK)       // 1084

#define MINL (-150.0f)
#define MAXL (150.0f)
#define DXF  (300.0f/63.0f)

// partial moments: [tile][b][k] = (sum e, sum e*x, sum e*y, sum e*(x^2+y^2))
__device__ float4 g_part[TILES][B_][K_];
// z results: [b][k] = (loc_z, var_z)
__device__ float2 g_zres[B_][K_];
// two-level completion counters (zero-init; reset in-kernel for graph replay)
__device__ unsigned int g_cnt8[8 * 32];   // 128B apart
__device__ unsigned int g_master;

__constant__ int c_limb[K_] = {0,0,1,1,1,3,4,5,6,2,2,9,10,11,12};
__constant__ int c_sym [K_] = {0,1,2,4,3,6,5,8,7,10,9,12,11,14,13};

// ---------------------------------------------------------------------------
__device__ __forceinline__ float2 block_sum512_2(float2 v) {
    __shared__ float2 sm[16];
    const int tid = threadIdx.x;
#pragma unroll
    for (int o = 16; o > 0; o >>= 1) {
        v.x += __shfl_down_sync(0xffffffffu, v.x, o);
        v.y += __shfl_down_sync(0xffffffffu, v.y, o);
    }
    __syncthreads();
    if ((tid & 31) == 0) sm[tid >> 5] = v;
    __syncthreads();
    float2 w = make_float2(0.f, 0.f);
    if (tid < 32) {
        if (tid < 16) w = sm[tid];
#pragma unroll
        for (int o = 8; o > 0; o >>= 1) {
            w.x += __shfl_down_sync(0xffffffffu, w.x, o);
            w.y += __shfl_down_sync(0xffffffffu, w.y, o);
        }
        if (tid == 0) sm[0] = w;
    }
    __syncthreads();
    return sm[0];
}

// ---------------------------------------------------------------------------
// Final phase; smem arrays alias the tile staging buffer (scratch).
// ---------------------------------------------------------------------------
__device__ void final_phase(const float* __restrict__ gt,
                            float* __restrict__ out,
                            int total_off, int pose_off,
                            char* scratch) {
    const int tid = threadIdx.x;
    const bool act = (tid < B_ * K_);
    const int b = tid / K_;
    const int k = tid - b * K_;

    int*   s_idx = (int*)  (scratch);            // 480 ints
    float* s_gtz = (float*)(scratch + 1920 * 1);
    float* s_px  = (float*)(scratch + 1920 * 2);
    float* s_py  = (float*)(scratch + 1920 * 3);
    float* s_pz  = (float*)(scratch + 1920 * 4);
    float* s_vx  = (float*)(scratch + 1920 * 5);
    float* s_pxx = (float*)(scratch + 1920 * 6);
    float* s_vz  = (float*)(scratch + 1920 * 7);
    float* s_pzz = (float*)(scratch + 1920 * 8);
    float* s_lp  = (float*)(scratch + 1920 * 9);

    float gtx = 0.f, gty = 0.f, gtzc = 0.f;
    float locx = 0.f, locy = 0.f, varxy = 0.f, posxy = 0.f;
    float locz = 0.f, varz = 0.f, posz = 0.f;
    if (act) {
        const float* g3 = gt + tid * 3;
        gtx  = fminf(fmaxf(g3[0], MINL), MAXL);
        gty  = fminf(fmaxf(g3[1], MINL), MAXL);
        gtzc = fminf(fmaxf(g3[2], MINL), MAXL);
        int ix = min(max((int)rintf((gtx - MINL) / DXF), 0), H_ - 1);
        int iy = min(max((int)rintf((gty - MINL) / DXF), 0), W_ - 1);
        s_idx[tid] = ix * W_ + iy;
        s_gtz[tid] = gtzc;

        float4 S = make_float4(0.f, 0.f, 0.f, 0.f);
#pragma unroll
        for (int t = 0; t < TILES; ++t) {
            float4 q = g_part[t][b][k];
            S.x += q.x; S.y += q.y; S.z += q.z; S.w += q.w;
        }
        locx  = S.y / S.x;
        locy  = S.z / S.x;
        varxy = S.w / S.x - locx * locx - locy * locy;
        const float dx0 = locx - gtx, dy0 = locy - gty;
        posxy = dx0 * dx0 + dy0 * dy0;
        s_px[tid] = locx; s_py[tid] = locy;
        s_vx[tid] = varxy; s_pxx[tid] = posxy;

        const float2 zr = g_zres[b][k];
        locz = zr.x; varz = zr.y;
    }
    __syncthreads();

    if (act) {
        // gt_exp scatter with duplicate pixel indices: last k wins
        float gte = gtzc;
        const int me = s_idx[tid];
        const int b0 = b * K_;
        for (int kk = 0; kk < K_; ++kk)
            if (s_idx[b0 + kk] == me) gte = s_gtz[b0 + kk];
        const float d = locz - gte;
        posz = d * d;
        s_pz[tid]  = locz;
        s_vz[tid]  = varz;
        s_pzz[tid] = posz;
    }
    __syncthreads();

    const float2 stot = block_sum512_2(
        act ? make_float2(varxy + posxy, varz + posz) : make_float2(0.f, 0.f));
    const float s_xy_tot = stot.x + 0.001f;
    const float s_z_tot  = stot.y + 0.001f;

    float2 colsq = make_float2(0.f, 0.f);
    if (tid < K_) {
        float cvx = 0.f, cpx = 0.f, cvz = 0.f, cpz = 0.f;
        for (int bb = 0; bb < B_; ++bb) {
            const int i = bb * K_ + tid;
            cvx += s_vx[i];  cpx += s_pxx[i];
            cvz += s_vz[i];  cpz += s_pzz[i];
        }
        colsq = make_float2(cvx * cvx + cpx * cpx, cvz * cvz + cpz * cpz);
    }
    const float2 csum = block_sum512_2(colsq);
    const float hxy = csum.x * (float)K_ / (s_xy_tot * MAXL);
    const float hz  = csum.y * (float)K_ / (s_z_tot  * MAXL);

    float ll = 0.f;
    if (act) {
        const int par = b * K_ + c_limb[k];
        const float dxp = locx - s_px[par];
        const float dyp = locy - s_py[par];
        const float dzp = locz - s_pz[par];
        const float lp = sqrtf(dxp * dxp + dyp * dyp + dzp * dzp + 1e-12f);
        const float* g3 = gt + tid * 3;
        const float* gp = gt + par * 3;
        const float dgx = g3[0] - gp[0], dgy = g3[1] - gp[1], dgz = g3[2] - gp[2];
        const float lg = sqrtf(dgx * dgx + dgy * dgy + dgz * dgz + 1e-12f);
        const float dl = lp - lg;
        ll = dl * dl;
        s_lp[tid] = lp;
    }
    __syncthreads();
    if (act) {
        const float ds = s_lp[tid] - s_lp[b * K_ + c_sym[k]];
        ll += ds * ds;
    }
    const float2 lsum = block_sum512_2(make_float2(ll, 0.f));
    const float limbsym = lsum.x;

    if (tid == 0 && total_off >= 0) out[total_off] = hxy + hz + limbsym;
    if (act && pose_off >= 0) {
        float* o = out + pose_off + tid * 3;
        o[0] = locx; o[1] = locy; o[2] = locz;
    }
}

// ---------------------------------------------------------------------------
// Fused kernel. z blocks first; xy blocks stream a 128-pixel tile densely
// (coalesced float4), compute moments from smem. Last block finalizes.
// ---------------------------------------------------------------------------
__global__ void __launch_bounds__(512)
k_fused(const float* __restrict__ feat, const float* __restrict__ gt,
        float* __restrict__ out, int total_off, int pose_off) {
    const int tid = threadIdx.x;
    const int blk = blockIdx.x;

    __shared__ float s_tile[TILE_WORDS];         // 40448 B staging / final scratch
    __shared__ float4 sm4[16][16];

    if (blk >= NZBLK) {
        // ---------------- xy tile: dense load + moments ----------------
        const int xyi  = blk - NZBLK;
        const int b    = xyi >> 5;        // 0..31
        const int tile = xyi & 31;        // 0..31
        const int pix0 = tile * TILE_PIX;

        // dense, perfectly coalesced float4 streaming of the whole tile
        const float4* src = (const float4*)(feat + (size_t)(b * NPIX + pix0) * NCH);
        float4* dst = (float4*)s_tile;
#pragma unroll
        for (int i = 0; i < 4; ++i)
            dst[tid + i * 512] = src[tid + i * 512];
        if (tid < TILE_F4 - 4 * 512)
            dst[tid + 4 * 512] = src[tid + 4 * 512];
        __syncthreads();

        // compute: c = channel (15 dummy), g covers 4 pixels
        const int c = tid & 15;
        const int g = tid >> 4;           // 0..31
        float S0 = 0.f, S1x = 0.f, S1y = 0.f, S2 = 0.f;
#pragma unroll
        for (int h = 0; h < 4; ++h) {
            const int pl = h * 32 + g;
            const int p  = pix0 + pl;
            const float e = __expf(s_tile[pl * NCH + c]);
            const float x = MINL + (float)(p >> 6) * DXF;
            const float y = MINL + (float)(p & 63) * DXF;
            S0 += e;
            S1x = fmaf(e, x, S1x);
            S1y = fmaf(e, y, S1y);
            S2  = fmaf(e, fmaf(x, x, y * y), S2);
        }

        S0  += __shfl_down_sync(0xffffffffu, S0, 16);
        S1x += __shfl_down_sync(0xffffffffu, S1x, 16);
        S1y += __shfl_down_sync(0xffffffffu, S1y, 16);
        S2  += __shfl_down_sync(0xffffffffu, S2, 16);

        if ((tid & 31) < 16) sm4[tid >> 5][c] = make_float4(S0, S1x, S1y, S2);
        __syncthreads();
        if (tid < K_) {
            float4 A = make_float4(0.f, 0.f, 0.f, 0.f);
#pragma unroll
            for (int w = 0; w < 16; ++w) {
                const float4 q = sm4[w][tid];
                A.x += q.x; A.y += q.y; A.z += q.z; A.w += q.w;
            }
            g_part[tile][b][tid] = A;
        }
    } else {
        // ---------------- z softmax: 8 (b,k) per block ----------------
        const int zi = blk;
        const int s  = tid >> 6;
        const int zb = tid & 63;
        const int bk = zi * 8 + s;
        const int b  = bk / K_;
        const int k  = bk - b * K_;

        __shared__ int s_pix[8];
        if (zb == 0) {
            const float* g3 = gt + bk * 3;
            const float gtx = fminf(fmaxf(g3[0], MINL), MAXL);
            const float gty = fminf(fmaxf(g3[1], MINL), MAXL);
            int ix = min(max((int)rintf((gtx - MINL) / DXF), 0), H_ - 1);
            int iy = min(max((int)rintf((gty - MINL) / DXF), 0), W_ - 1);
            s_pix[s] = ix * W_ + iy;
        }
        __syncthreads();

        const float* fz = feat + ((size_t)(b * NPIX + s_pix[s])) * NCH + K_;
        const float e  = __expf(fz[zb]);
        const float zm = MINL + (float)zb * DXF;
        float S0 = e;
        float S1 = e * zm;
        float S2 = e * zm * zm;

#pragma unroll
        for (int o = 16; o > 0; o >>= 1) {
            S0 += __shfl_down_sync(0xffffffffu, S0, o);
            S1 += __shfl_down_sync(0xffffffffu, S1, o);
            S2 += __shfl_down_sync(0xffffffffu, S2, o);
        }
        __shared__ float3 ws[16];
        if ((tid & 31) == 0) ws[tid >> 5] = make_float3(S0, S1, S2);
        __syncthreads();
        if (zb == 0) {
            const float3 a = ws[2 * s], q = ws[2 * s + 1];
            const float T0 = a.x + q.x;
            const float T1 = a.y + q.y;
            const float T2 = a.z + q.z;
            const float locz = T1 / T0;
            const float varz = T2 / T0 - locz * locz;
            g_zres[b][k] = make_float2(locz, varz);
        }
    }

    // ---------------- two-level completion protocol ----------------
    __threadfence();
    __shared__ bool s_last;
    if (tid == 0) {
        bool last = false;
        const int r = blk & 7;
        const unsigned int gsz = (unsigned int)((NBLK - 1 - r) / 8 + 1);
        const unsigned int prev = atomicAdd(&g_cnt8[r * 32], 1u);
        if (prev == gsz - 1u) {
            g_cnt8[r * 32] = 0;
            __threadfence();
            const unsigned int mp = atomicAdd(&g_master, 1u);
            if (mp == 7u) { last = true; g_master = 0; }
        }
        s_last = last;
    }
    __syncthreads();

    if (s_last) {
        __threadfence();
        final_phase(gt, out, total_off, pose_off, (char*)s_tile);
    }
}

// ---------------------------------------------------------------------------
extern "C" void kernel_launch(void* const* d_in, const int* in_sizes, int n_in,
                              void* d_out, int out_size) {
    const float* feat = (const float*)d_in[0];   // (32,64,64,79)
    const float* gt   = (const float*)d_in[1];   // (32,15,3)
    float* out = (float*)d_out;

    int total_off, pose_off;
    if (out_size >= 1441)      { total_off = 0;  pose_off = 1;  }
    else if (out_size == 1440) { total_off = -1; pose_off = 0;  }
    else                       { total_off = 0;  pose_off = -1; }

    k_fused<<<NBLK, 512>>>(feat, gt, out, total_off, pose_off);
}

// round 14
// speedup vs baseline: 1.4978x; 1.4978x over previous
#include <cuda_runtime.h>

#define B_    32
#define H_    64
#define W_    64
#define K_    15
#define ZB_   64
#define NPIX  4096
#define NCH   79
#define CHUNKS 2
#define PIX_PER_CHUNK 2048

#define NZBLK  60                 // z blocks scheduled first
#define NXYBLK (CHUNKS * B_)      // 64
#define NBLK   (NZBLK + NXYBLK)   // 124  (<= 148 SMs: one block per SM)

#define MINL (-150.0f)
#define MAXL (150.0f)
#define DXF  (300.0f/63.0f)

// partial moments: [chunk][b][k] = (sum e, sum e*x, sum e*y, sum e*(x^2+y^2))
__device__ float4 g_part[CHUNKS][B_][K_];
// z results: [b][k] = (loc_z, var_z)
__device__ float2 g_zres[B_][K_];
// two-level completion counters (zero-initialized; reset in-kernel for replay)
__device__ unsigned int g_cnt8[8 * 32];   // stride 32 ints = 128B apart
__device__ unsigned int g_master;

__constant__ int c_limb[K_] = {0,0,1,1,1,3,4,5,6,2,2,9,10,11,12};
__constant__ int c_sym [K_] = {0,1,2,4,3,6,5,8,7,10,9,12,11,14,13};

// ---------------------------------------------------------------------------
// Block-wide float2 sum over 512 threads via shuffles; 3 barriers.
// ---------------------------------------------------------------------------
__device__ __forceinline__ float2 block_sum512_2(float2 v) {
    __shared__ float2 sm[16];
    const int tid = threadIdx.x;
#pragma unroll
    for (int o = 16; o > 0; o >>= 1) {
        v.x += __shfl_down_sync(0xffffffffu, v.x, o);
        v.y += __shfl_down_sync(0xffffffffu, v.y, o);
    }
    __syncthreads();                       // protect sm reuse across calls
    if ((tid & 31) == 0) sm[tid >> 5] = v;
    __syncthreads();
    float2 w = make_float2(0.f, 0.f);
    if (tid < 32) {
        if (tid < 16) w = sm[tid];
#pragma unroll
        for (int o = 8; o > 0; o >>= 1) {
            w.x += __shfl_down_sync(0xffffffffu, w.x, o);
            w.y += __shfl_down_sync(0xffffffffu, w.y, o);
        }
        if (tid == 0) sm[0] = w;
    }
    __syncthreads();
    return sm[0];
}

// ---------------------------------------------------------------------------
// Final phase: executed by the globally-last block (512 threads).
// ---------------------------------------------------------------------------
__device__ void final_phase(const float* __restrict__ gt,
                            float* __restrict__ out,
                            int total_off, int pose_off) {
    const int tid = threadIdx.x;
    const bool act = (tid < B_ * K_);
    const int b = tid / K_;
    const int k = tid - b * K_;

    __shared__ int   s_idx[B_][K_];
    __shared__ float s_gtz[B_][K_];
    __shared__ float s_px[B_][K_], s_py[B_][K_], s_pz[B_][K_];
    __shared__ float s_vx[B_][K_], s_pxx[B_][K_];
    __shared__ float s_vz[B_][K_], s_pzz[B_][K_];
    __shared__ float s_lp[B_][K_];

    float gtx = 0.f, gty = 0.f, gtzc = 0.f;
    float locx = 0.f, locy = 0.f, varxy = 0.f, posxy = 0.f;
    float locz = 0.f, varz = 0.f, posz = 0.f;
    if (act) {
        const float* g3 = gt + (b * K_ + k) * 3;
        gtx  = fminf(fmaxf(g3[0], MINL), MAXL);
        gty  = fminf(fmaxf(g3[1], MINL), MAXL);
        gtzc = fminf(fmaxf(g3[2], MINL), MAXL);
        int ix = min(max((int)rintf((gtx - MINL) / DXF), 0), H_ - 1);
        int iy = min(max((int)rintf((gty - MINL) / DXF), 0), W_ - 1);
        s_idx[b][k] = ix * W_ + iy;
        s_gtz[b][k] = gtzc;

        float4 S = make_float4(0.f, 0.f, 0.f, 0.f);
#pragma unroll
        for (int chn = 0; chn < CHUNKS; ++chn) {
            float4 q = g_part[chn][b][k];
            S.x += q.x; S.y += q.y; S.z += q.z; S.w += q.w;
        }
        locx  = S.y / S.x;
        locy  = S.z / S.x;
        varxy = S.w / S.x - locx * locx - locy * locy;
        const float dx0 = locx - gtx, dy0 = locy - gty;
        posxy = dx0 * dx0 + dy0 * dy0;
        s_px[b][k]  = locx; s_py[b][k] = locy;
        s_vx[b][k]  = varxy; s_pxx[b][k] = posxy;

        const float2 zr = g_zres[b][k];
        locz = zr.x; varz = zr.y;
    }
    __syncthreads();

    if (act) {
        // gt_exp scatter with duplicate pixel indices: last k wins
        float gte = gtzc;
        const int me = s_idx[b][k];
        for (int kk = 0; kk < K_; ++kk)
            if (s_idx[b][kk] == me) gte = s_gtz[b][kk];
        const float d = locz - gte;
        posz = d * d;
        s_pz[b][k]  = locz;
        s_vz[b][k]  = varz;
        s_pzz[b][k] = posz;
    }
    __syncthreads();

    const float2 stot = block_sum512_2(
        act ? make_float2(varxy + posxy, varz + posz) : make_float2(0.f, 0.f));
    const float s_xy_tot = stot.x + 0.001f;
    const float s_z_tot  = stot.y + 0.001f;

    float2 colsq = make_float2(0.f, 0.f);
    if (tid < K_) {
        float cvx = 0.f, cpx = 0.f, cvz = 0.f, cpz = 0.f;
        for (int bb = 0; bb < B_; ++bb) {
            cvx += s_vx[bb][tid];  cpx += s_pxx[bb][tid];
            cvz += s_vz[bb][tid];  cpz += s_pzz[bb][tid];
        }
        colsq = make_float2(cvx * cvx + cpx * cpx, cvz * cvz + cpz * cpz);
    }
    const float2 csum = block_sum512_2(colsq);
    const float hxy = csum.x * (float)K_ / (s_xy_tot * MAXL);
    const float hz  = csum.y * (float)K_ / (s_z_tot  * MAXL);

    float ll = 0.f;
    if (act) {
        const int par = c_limb[k];
        const float dxp = locx - s_px[b][par];
        const float dyp = locy - s_py[b][par];
        const float dzp = locz - s_pz[b][par];
        const float lp = sqrtf(dxp * dxp + dyp * dyp + dzp * dzp + 1e-12f);
        const float* g3 = gt + (b * K_ + k) * 3;
        const float* gp = gt + (b * K_ + par) * 3;
        const float dgx = g3[0] - gp[0], dgy = g3[1] - gp[1], dgz = g3[2] - gp[2];
        const float lg = sqrtf(dgx * dgx + dgy * dgy + dgz * dgz + 1e-12f);
        const float dl = lp - lg;
        ll = dl * dl;
        s_lp[b][k] = lp;
    }
    __syncthreads();
    if (act) {
        const float ds = s_lp[b][k] - s_lp[b][c_sym[k]];
        ll += ds * ds;
    }
    const float2 lsum = block_sum512_2(make_float2(ll, 0.f));
    const float limbsym = lsum.x;

    if (tid == 0 && total_off >= 0) out[total_off] = hxy + hz + limbsym;
    if (act && pose_off >= 0) {
        float* o = out + pose_off + (b * K_ + k) * 3;
        o[0] = locx; o[1] = locy; o[2] = locz;
    }
}

// ---------------------------------------------------------------------------
// Fused kernel. 124 blocks (one per SM): 60 z blocks first, then 64 xy
// blocks; each xy thread covers 64 pixels in two 32-deep LDG batches.
// ---------------------------------------------------------------------------
__global__ void __launch_bounds__(512, 2)
k_fused(const float* __restrict__ feat, const float* __restrict__ gt,
        float* __restrict__ out, int total_off, int pose_off) {
    const int tid = threadIdx.x;
    const int blk = blockIdx.x;

    if (blk >= NZBLK) {
        // ---------------- xy partial moments ----------------
        const int xyi   = blk - NZBLK;
        const int b     = xyi >> 1;       // 0..31
        const int chunk = xyi & 1;        // 0..1
        const int c     = tid & 15;       // channel (15 is a dummy lane)
        const int g     = tid >> 4;       // pixel group 0..31

        float S0 = 0.f, S1x = 0.f, S1y = 0.f, S2 = 0.f;
#pragma unroll 1
        for (int half = 0; half < 2; ++half) {
            const int pbase = chunk * PIX_PER_CHUNK + half * 1024;
            const float* base = feat + (size_t)(b * NPIX + pbase + g) * NCH + c;
            float vals[32];
#pragma unroll
            for (int it = 0; it < 32; ++it)
                vals[it] = base[(size_t)it * 32 * NCH];
#pragma unroll
            for (int it = 0; it < 32; ++it) {
                const int p = pbase + it * 32 + g;
                const float e = __expf(vals[it]);
                const float x = MINL + (float)(p >> 6) * DXF;
                const float y = MINL + (float)(p & 63) * DXF;
                S0 += e;
                S1x = fmaf(e, x, S1x);
                S1y = fmaf(e, y, S1y);
                S2  = fmaf(e, fmaf(x, x, y * y), S2);
            }
        }

        // reduce over g: warp shuffle (two g per warp), then 16 warps by 15 thr
        S0  += __shfl_down_sync(0xffffffffu, S0, 16);
        S1x += __shfl_down_sync(0xffffffffu, S1x, 16);
        S1y += __shfl_down_sync(0xffffffffu, S1y, 16);
        S2  += __shfl_down_sync(0xffffffffu, S2, 16);

        __shared__ float4 sm4[16][16];
        if ((tid & 31) < 16) sm4[tid >> 5][c] = make_float4(S0, S1x, S1y, S2);
        __syncthreads();
        if (tid < K_) {
            float4 A = make_float4(0.f, 0.f, 0.f, 0.f);
#pragma unroll
            for (int w = 0; w < 16; ++w) {
                const float4 q = sm4[w][tid];
                A.x += q.x; A.y += q.y; A.z += q.z; A.w += q.w;
            }
            g_part[chunk][b][tid] = A;
        }
    } else {
        // ---------------- z softmax: 8 (b,k) per block ----------------
        const int zi = blk;               // 0..59
        const int s  = tid >> 6;          // sub-block 0..7
        const int zb = tid & 63;          // z bin
        const int bk = zi * 8 + s;        // 0..479
        const int b  = bk / K_;
        const int k  = bk - b * K_;

        __shared__ int s_pix[8];
        if (zb == 0) {
            const float* g3 = gt + bk * 3;
            const float gtx = fminf(fmaxf(g3[0], MINL), MAXL);
            const float gty = fminf(fmaxf(g3[1], MINL), MAXL);
            int ix = min(max((int)rintf((gtx - MINL) / DXF), 0), H_ - 1);
            int iy = min(max((int)rintf((gty - MINL) / DXF), 0), W_ - 1);
            s_pix[s] = ix * W_ + iy;
        }
        __syncthreads();

        const float* fz = feat + ((size_t)(b * NPIX + s_pix[s])) * NCH + K_;
        const float e  = __expf(fz[zb]);
        const float zm = MINL + (float)zb * DXF;
        float S0 = e;
        float S1 = e * zm;
        float S2 = e * zm * zm;

#pragma unroll
        for (int o = 16; o > 0; o >>= 1) {
            S0 += __shfl_down_sync(0xffffffffu, S0, o);
            S1 += __shfl_down_sync(0xffffffffu, S1, o);
            S2 += __shfl_down_sync(0xffffffffu, S2, o);
        }
        __shared__ float3 ws[16];
        if ((tid & 31) == 0) ws[tid >> 5] = make_float3(S0, S1, S2);
        __syncthreads();
        if (zb == 0) {
            const float3 a = ws[2 * s], q = ws[2 * s + 1];
            const float T0 = a.x + q.x;
            const float T1 = a.y + q.y;
            const float T2 = a.z + q.z;
            const float locz = T1 / T0;
            const float varz = T2 / T0 - locz * locz;
            g_zres[b][k] = make_float2(locz, varz);
        }
    }

    // ---------------- two-level completion protocol ----------------
    __threadfence();
    __shared__ bool s_last;
    if (tid == 0) {
        bool last = false;
        const int r = blk & 7;
        const unsigned int gsz = (unsigned int)((NBLK - 1 - r) / 8 + 1);
        const unsigned int prev = atomicAdd(&g_cnt8[r * 32], 1u);
        if (prev == gsz - 1u) {
            g_cnt8[r * 32] = 0;                    // reset own group counter
            __threadfence();
            const unsigned int mp = atomicAdd(&g_master, 1u);
            if (mp == 7u) { last = true; g_master = 0; }
        }
        s_last = last;
    }
    __syncthreads();

    if (s_last) {
        __threadfence();
        final_phase(gt, out, total_off, pose_off);
    }
}

// ---------------------------------------------------------------------------
extern "C" void kernel_launch(void* const* d_in, const int* in_sizes, int n_in,
                              void* d_out, int out_size) {
    const float* feat = (const float*)d_in[0];   // (32,64,64,79)
    const float* gt   = (const float*)d_in[1];   // (32,15,3)
    float* out = (float*)d_out;

    int total_off, pose_off;
    if (out_size >= 1441)      { total_off = 0;  pose_off = 1;  }
    else if (out_size == 1440) { total_off = -1; pose_off = 0;  }
    else                       { total_off = 0;  pose_off = -1; }

    k_fused<<<NBLK, 512>>>(feat, gt, out, total_off, pose_off);
}

// round 15
// speedup vs baseline: 1.7577x; 1.1735x over previous
#include <cuda_runtime.h>

#define B_    32
#define H_    64
#define W_    64
#define K_    15
#define ZB_   64
#define NPIX  4096
#define NCH   79
#define CHUNKS 4
#define PIX_PER_CHUNK 1024

#define NZBLK   60
#define NXYBLK  (CHUNKS * B_)          // 128
#define NBLK    (1 + NZBLK + NXYBLK)   // 189 (finalizer + producers)

#define MINL (-150.0f)
#define MAXL (150.0f)
#define DXF  (300.0f/63.0f)

// partial moments: [chunk][b][k] = (sum e, sum e*x, sum e*y, sum e*(x^2+y^2))
__device__ float4 g_part[CHUNKS][B_][K_];
// z results: [b][k] = (loc_z, var_z)
__device__ float2 g_zres[B_][K_];
// phase counters (zero-initialized; finalizer resets at end of each run)
__device__ unsigned int g_zcnt;
__device__ unsigned int g_xycnt;

__constant__ int c_limb[K_] = {0,0,1,1,1,3,4,5,6,2,2,9,10,11,12};
__constant__ int c_sym [K_] = {0,1,2,4,3,6,5,8,7,10,9,12,11,14,13};

// ---------------------------------------------------------------------------
// Block-wide float2 sum over 512 threads via shuffles; 3 barriers.
// ---------------------------------------------------------------------------
__device__ __forceinline__ float2 block_sum512_2(float2 v) {
    __shared__ float2 sm[16];
    const int tid = threadIdx.x;
#pragma unroll
    for (int o = 16; o > 0; o >>= 1) {
        v.x += __shfl_down_sync(0xffffffffu, v.x, o);
        v.y += __shfl_down_sync(0xffffffffu, v.y, o);
    }
    __syncthreads();                       // protect sm reuse across calls
    if ((tid & 31) == 0) sm[tid >> 5] = v;
    __syncthreads();
    float2 w = make_float2(0.f, 0.f);
    if (tid < 32) {
        if (tid < 16) w = sm[tid];
#pragma unroll
        for (int o = 8; o > 0; o >>= 1) {
            w.x += __shfl_down_sync(0xffffffffu, w.x, o);
            w.y += __shfl_down_sync(0xffffffffu, w.y, o);
        }
        if (tid == 0) sm[0] = w;
    }
    __syncthreads();
    return sm[0];
}

// ---------------------------------------------------------------------------
// Spin until *cnt reaches target; then block barrier + fence.
// ---------------------------------------------------------------------------
__device__ __forceinline__ void wait_count(volatile unsigned int* cnt,
                                           unsigned int target) {
    if (threadIdx.x == 0) {
        while (*cnt < target) { __nanosleep(64); }
    }
    __syncthreads();
    __threadfence();
}

// ---------------------------------------------------------------------------
// Finalizer block: overlaps gt-side + z-side work with xy producers.
// ---------------------------------------------------------------------------
__device__ void finalizer(const float* __restrict__ gt,
                          float* __restrict__ out,
                          int total_off, int pose_off) {
    const int tid = threadIdx.x;
    const bool act = (tid < B_ * K_);
    const int b = tid / K_;
    const int k = tid - b * K_;

    __shared__ int   s_idx[B_ * K_];
    __shared__ float s_gtz[B_ * K_];
    __shared__ float s_px[B_ * K_], s_py[B_ * K_], s_pz[B_ * K_];
    __shared__ float s_vx[B_ * K_], s_pxx[B_ * K_];
    __shared__ float s_vz[B_ * K_], s_pzz[B_ * K_];
    __shared__ float s_lp[B_ * K_];

    // ================= Phase A: gt-only work (no producer deps) ============
    float gtx = 0.f, gty = 0.f, gtzc = 0.f, lg = 0.f;
    int par = 0;
    if (act) {
        const float* g3 = gt + tid * 3;
        gtx  = fminf(fmaxf(g3[0], MINL), MAXL);
        gty  = fminf(fmaxf(g3[1], MINL), MAXL);
        gtzc = fminf(fmaxf(g3[2], MINL), MAXL);
        int ix = min(max((int)rintf((gtx - MINL) / DXF), 0), H_ - 1);
        int iy = min(max((int)rintf((gty - MINL) / DXF), 0), W_ - 1);
        s_idx[tid] = ix * W_ + iy;
        s_gtz[tid] = gtzc;

        par = b * K_ + c_limb[k];
        const float* gp = gt + par * 3;
        const float dgx = g3[0] - gp[0], dgy = g3[1] - gp[1], dgz = g3[2] - gp[2];
        lg = sqrtf(dgx * dgx + dgy * dgy + dgz * dgz + 1e-12f);
    }
    __syncthreads();

    float gte = gtzc;
    if (act) {
        // gt_exp scatter with duplicate pixel indices: last k wins
        const int me = s_idx[tid];
        const int b0 = b * K_;
        for (int kk = 0; kk < K_; ++kk)
            if (s_idx[b0 + kk] == me) gte = s_gtz[b0 + kk];
    }

    // ================= Phase B: z-side (needs z producers only) ============
    wait_count(&g_zcnt, NZBLK);

    float locz = 0.f, varz = 0.f, posz = 0.f;
    if (act) {
        const float2 zr = g_zres[b][k];
        locz = zr.x; varz = zr.y;
        const float d = locz - gte;
        posz = d * d;
        s_pz[tid]  = locz;
        s_vz[tid]  = varz;
        s_pzz[tid] = posz;
    }
    __syncthreads();

    float colsq_z = 0.f;
    if (tid < K_) {
        float cv = 0.f, cp = 0.f;
        for (int bb = 0; bb < B_; ++bb) {
            cv += s_vz[bb * K_ + tid];  cp += s_pzz[bb * K_ + tid];
        }
        colsq_z = cv * cv + cp * cp;
    }
    const float2 zred = block_sum512_2(
        make_float2(act ? (varz + posz) : 0.f, colsq_z));
    const float hz = zred.y * (float)K_ / ((zred.x + 0.001f) * MAXL);

    // ================= Phase C: xy-side (needs all xy producers) ===========
    wait_count(&g_xycnt, NXYBLK);

    float locx = 0.f, locy = 0.f, varxy = 0.f, posxy = 0.f;
    if (act) {
        float4 S = make_float4(0.f, 0.f, 0.f, 0.f);
#pragma unroll
        for (int chn = 0; chn < CHUNKS; ++chn) {
            float4 q = g_part[chn][b][k];
            S.x += q.x; S.y += q.y; S.z += q.z; S.w += q.w;
        }
        locx  = S.y / S.x;
        locy  = S.z / S.x;
        varxy = S.w / S.x - locx * locx - locy * locy;
        const float dx0 = locx - gtx, dy0 = locy - gty;
        posxy = dx0 * dx0 + dy0 * dy0;
        s_px[tid]  = locx; s_py[tid] = locy;
        s_vx[tid]  = varxy; s_pxx[tid] = posxy;
        // pose output early (off critical path)
        if (pose_off >= 0) {
            float* o = out + pose_off + tid * 3;
            o[0] = locx; o[1] = locy; o[2] = locz;
        }
    }
    __syncthreads();

    float colsq_x = 0.f;
    if (tid < K_) {
        float cv = 0.f, cp = 0.f;
        for (int bb = 0; bb < B_; ++bb) {
            cv += s_vx[bb * K_ + tid];  cp += s_pxx[bb * K_ + tid];
        }
        colsq_x = cv * cv + cp * cp;
    }
    const float2 xred = block_sum512_2(
        make_float2(act ? (varxy + posxy) : 0.f, colsq_x));
    const float hxy = xred.y * (float)K_ / ((xred.x + 0.001f) * MAXL);

    // limb + sym losses
    float ll = 0.f;
    if (act) {
        const float dxp = locx - s_px[par];
        const float dyp = locy - s_py[par];
        const float dzp = locz - s_pz[par];
        const float lp = sqrtf(dxp * dxp + dyp * dyp + dzp * dzp + 1e-12f);
        const float dl = lp - lg;
        ll = dl * dl;
        s_lp[tid] = lp;
    }
    __syncthreads();
    if (act) {
        const float ds = s_lp[tid] - s_lp[b * K_ + c_sym[k]];
        ll += ds * ds;
    }
    const float2 lsum = block_sum512_2(make_float2(ll, 0.f));

    if (tid == 0) {
        if (total_off >= 0) out[total_off] = hxy + hz + lsum.x;
        g_zcnt = 0;                      // reset for next graph replay
        g_xycnt = 0;
    }
}

// ---------------------------------------------------------------------------
// Fused kernel: block 0 = finalizer; 1..60 = z; 61..188 = xy producers.
// ---------------------------------------------------------------------------
__global__ void __launch_bounds__(512, 2)
k_fused(const float* __restrict__ feat, const float* __restrict__ gt,
        float* __restrict__ out, int total_off, int pose_off) {
    const int tid = threadIdx.x;
    const int blk = blockIdx.x;

    if (blk == 0) {
        finalizer(gt, out, total_off, pose_off);
        return;
    }

    if (blk > NZBLK) {
        // ---------------- xy partial moments ----------------
        const int xyi   = blk - 1 - NZBLK;
        const int b     = xyi >> 2;       // 0..31
        const int chunk = xyi & 3;        // 0..3
        const int c     = tid & 15;       // channel (15 is a dummy lane)
        const int g     = tid >> 4;       // pixel group 0..31

        float S0 = 0.f, S1x = 0.f, S1y = 0.f, S2 = 0.f;
#pragma unroll 1
        for (int half = 0; half < 2; ++half) {
            const int pbase = chunk * PIX_PER_CHUNK + half * 512;
            const float* base = feat + (size_t)(b * NPIX + pbase + g) * NCH + c;
            float vals[16];
#pragma unroll
            for (int it = 0; it < 16; ++it)
                vals[it] = base[(size_t)it * 32 * NCH];
#pragma unroll
            for (int it = 0; it < 16; ++it) {
                const int p = pbase + it * 32 + g;
                const float e = __expf(vals[it]);
                const float x = MINL + (float)(p >> 6) * DXF;
                const float y = MINL + (float)(p & 63) * DXF;
                S0 += e;
                S1x = fmaf(e, x, S1x);
                S1y = fmaf(e, y, S1y);
                S2  = fmaf(e, fmaf(x, x, y * y), S2);
            }
        }

        // reduce over g: warp shuffle (two g per warp), then 16 warps by 15 thr
        S0  += __shfl_down_sync(0xffffffffu, S0, 16);
        S1x += __shfl_down_sync(0xffffffffu, S1x, 16);
        S1y += __shfl_down_sync(0xffffffffu, S1y, 16);
        S2  += __shfl_down_sync(0xffffffffu, S2, 16);

        __shared__ float4 sm4[16][16];
        if ((tid & 31) < 16) sm4[tid >> 5][c] = make_float4(S0, S1x, S1y, S2);
        __syncthreads();
        if (tid < K_) {
            float4 A = make_float4(0.f, 0.f, 0.f, 0.f);
#pragma unroll
            for (int w = 0; w < 16; ++w) {
                const float4 q = sm4[w][tid];
                A.x += q.x; A.y += q.y; A.z += q.z; A.w += q.w;
            }
            g_part[chunk][b][tid] = A;
        }
        // completion
        __syncthreads();
        __threadfence();
        if (tid == 0) atomicAdd(&g_xycnt, 1u);
    } else {
        // ---------------- z softmax: 8 (b,k) per block ----------------
        const int zi = blk - 1;           // 0..59
        const int s  = tid >> 6;          // sub-block 0..7
        const int zb = tid & 63;          // z bin
        const int bk = zi * 8 + s;        // 0..479
        const int b  = bk / K_;
        const int k  = bk - b * K_;

        __shared__ int s_pix[8];
        if (zb == 0) {
            const float* g3 = gt + bk * 3;
            const float gtx = fminf(fmaxf(g3[0], MINL), MAXL);
            const float gty = fminf(fmaxf(g3[1], MINL), MAXL);
            int ix = min(max((int)rintf((gtx - MINL) / DXF), 0), H_ - 1);
            int iy = min(max((int)rintf((gty - MINL) / DXF), 0), W_ - 1);
            s_pix[s] = ix * W_ + iy;
        }
        __syncthreads();

        const float* fz = feat + ((size_t)(b * NPIX + s_pix[s])) * NCH + K_;
        const float e  = __expf(fz[zb]);
        const float zm = MINL + (float)zb * DXF;
        float S0 = e;
        float S1 = e * zm;
        float S2 = e * zm * zm;

#pragma unroll
        for (int o = 16; o > 0; o >>= 1) {
            S0 += __shfl_down_sync(0xffffffffu, S0, o);
            S1 += __shfl_down_sync(0xffffffffu, S1, o);
            S2 += __shfl_down_sync(0xffffffffu, S2, o);
        }
        __shared__ float3 ws[16];
        if ((tid & 31) == 0) ws[tid >> 5] = make_float3(S0, S1, S2);
        __syncthreads();
        if (zb == 0) {
            const float3 a = ws[2 * s], q = ws[2 * s + 1];
            const float T0 = a.x + q.x;
            const float T1 = a.y + q.y;
            const float T2 = a.z + q.z;
            const float locz = T1 / T0;
            const float varz = T2 / T0 - locz * locz;
            g_zres[b][k] = make_float2(locz, varz);
        }
        // completion
        __syncthreads();
        __threadfence();
        if (tid == 0) atomicAdd(&g_zcnt, 1u);
    }
}

// ---------------------------------------------------------------------------
extern "C" void kernel_launch(void* const* d_in, const int* in_sizes, int n_in,
                              void* d_out, int out_size) {
    const float* feat = (const float*)d_in[0];   // (32,64,64,79)
    const float* gt   = (const float*)d_in[1];   // (32,15,3)
    float* out = (float*)d_out;

    int total_off, pose_off;
    if (out_size >= 1441)      { total_off = 0;  pose_off = 1;  }
    else if (out_size == 1440) { total_off = -1; pose_off = 0;  }
    else                       { total_off = 0;  pose_off = -1; }

    k_fused<<<NBLK, 512>>>(feat, gt, out, total_off, pose_off);
}